// round 9
// baseline (speedup 1.0000x reference)
#include <cuda_runtime.h>
#include <cuda_bf16.h>

// CRF NLL, prob-domain forward. B=64, S=512, T=64 (START=62, END=63).
// R9: one warp per batch, bf16 everywhere. Lane owns columns (2j, 2j+1);
//     E pairs in 64 u32 regs; p in smem as duplicated bf16 pairs so LDS.128
//     feeds HFMA2 directly. Zero block barriers / zero shuffles in the hot
//     loop (1 syncwarp per step). Exact power-of-2 renorm per 8-step chunk.
//     4 warps/CTA (1 per SMSP), grid = 16.
//
// Inputs: d_in[0] feats f32 [B,S,T], d_in[1] transitions f32 [T,T],
//         d_in[2] mask i32 [B,S] (contiguous prefix), d_in[3] tags i32 [B,S]
// Output: f32 scalar sum_b (forward_b - gold_b)

#define B_    64
#define S_    512
#define T_    64
#define CHUNK 8
#define WPC   4

__device__ float g_res[B_];

static __device__ __forceinline__ __nv_bfloat162 u2b(unsigned u) {
    return *(__nv_bfloat162*)&u;
}

__global__ __launch_bounds__(WPC * 32, 1) void crf_forward_kernel(
    const float* __restrict__ feats,
    const float* __restrict__ trans,
    const int*   __restrict__ mask,
    const int*   __restrict__ tags)
{
    __shared__ __align__(16) float    trans_sh[T_ * T_];
    __shared__ __align__(16) unsigned p_sh[WPC][2][T_];   // dup bf16 pairs

    const int tid  = threadIdx.x;
    const int lane = tid & 31;
    const int wid  = tid >> 5;
    const int c0   = 2 * lane;                 // my two state columns
    const int b    = blockIdx.x * WPC + wid;

    const float* fb    = feats + (size_t)b * S_ * T_;
    const int*   maskb = mask  + b * S_;
    const int*   tagsb = tags  + b * S_;

    // ---- stage transitions (coalesced float4: 1024 float4 / 128 thr) ----
    {
        const float4* t4 = (const float4*)trans;
        float4*       s4 = (float4*)trans_sh;
        #pragma unroll
        for (int i = 0; i < 8; ++i) s4[i * 128 + tid] = t4[i * 128 + tid];
    }
    __syncthreads();   // only block-wide barrier

    // ---- per-warp length ----
    int len = 0;
    #pragma unroll
    for (int k = 0; k < 16; ++k) len += maskb[lane + 32 * k];
    #pragma unroll
    for (int o = 16; o; o >>= 1) len += __shfl_xor_sync(0xffffffffu, len, o);

    // ---- gold path score ----
    float gs = 0.f;
    #pragma unroll
    for (int k = 0; k < 16; ++k) {
        int s = lane + 32 * k;
        if (s < len) {
            int tg = tagsb[s];
            int pv = s ? tagsb[s - 1] : (T_ - 2);
            gs += fb[s * T_ + tg] + trans_sh[pv * T_ + tg];
        }
    }
    if (lane == 0) gs += trans_sh[tagsb[len - 1] * T_ + (T_ - 1)];
    #pragma unroll
    for (int o = 16; o; o >>= 1) gs += __shfl_xor_sync(0xffffffffu, gs, o);

    // ---- E pairs: e2[i] = (exp(trans[i][c0]), exp(trans[i][c0+1])) ----
    unsigned e2[T_];
    #pragma unroll
    for (int i = 0; i < T_; ++i) {
        float x = __expf(trans_sh[i * T_ + c0]);
        float y = __expf(trans_sh[i * T_ + c0 + 1]);
        __nv_bfloat162 t = __floats2bfloat162_rn(x, y);
        e2[i] = *(unsigned*)&t;
    }
    const float et0 = __expf(trans_sh[c0 * T_ + (T_ - 1)]);
    const float et1 = __expf(trans_sh[(c0 + 1) * T_ + (T_ - 1)]);

    // ---- init p_0 (my columns), store duplicated pairs ----
    __nv_bfloat162 q = __floats2bfloat162_rn(
        __expf(fb[c0]     + trans_sh[(T_ - 2) * T_ + c0]),
        __expf(fb[c0 + 1] + trans_sh[(T_ - 2) * T_ + c0 + 1]));
    {
        unsigned qu = *(unsigned*)&q;
        unsigned lo = __byte_perm(qu, qu, 0x1010);
        unsigned hi = __byte_perm(qu, qu, 0x3232);
        *(uint2*)&p_sh[wid][0][c0] = make_uint2(lo, hi);
    }
    __syncwarp();

    // ---- prefetch first chunk of emissions (steps 1..8) ----
    float2 fr[CHUNK], fr2[CHUNK];
    int c = 1;
    #pragma unroll
    for (int k = 0; k < CHUNK; ++k) {
        int s = min(c + k, S_ - 1);
        fr[k] = *(const float2*)(fb + s * T_ + c0);
    }

    // ---- forward recurrence (warp-synchronous, no barriers) ----
    int cur = 0, ksum = 0;

    while (c < len) {
        const int cnt = min(CHUNK, len - c);
        // prefetch next chunk
        {
            int nc = c + CHUNK;
            #pragma unroll
            for (int k = 0; k < CHUNK; ++k) {
                int s = min(nc + k, S_ - 1);
                fr2[k] = *(const float2*)(fb + s * T_ + c0);
            }
        }

        #pragma unroll
        for (int k = 0; k < CHUNK; ++k) {
            if (k >= cnt) break;   // warp-uniform
            __nv_bfloat162 f2 = __floats2bfloat162_rn(__expf(fr[k].x),
                                                      __expf(fr[k].y));
            const uint4* pv = (const uint4*)&p_sh[wid][cur][0];
            __nv_bfloat162 a0, a1, a2, a3;
            {
                uint4 u = pv[0];
                a0 = __hmul2(u2b(u.x), u2b(e2[0]));
                a1 = __hmul2(u2b(u.y), u2b(e2[1]));
                a2 = __hmul2(u2b(u.z), u2b(e2[2]));
                a3 = __hmul2(u2b(u.w), u2b(e2[3]));
            }
            #pragma unroll
            for (int m = 1; m < 16; ++m) {
                uint4 u = pv[m];
                a0 = __hfma2(u2b(u.x), u2b(e2[4 * m + 0]), a0);
                a1 = __hfma2(u2b(u.y), u2b(e2[4 * m + 1]), a1);
                a2 = __hfma2(u2b(u.z), u2b(e2[4 * m + 2]), a2);
                a3 = __hfma2(u2b(u.w), u2b(e2[4 * m + 3]), a3);
            }
            __nv_bfloat162 s2 = __hadd2(__hadd2(a0, a1), __hadd2(a2, a3));
            q = __hmul2(s2, f2);

            if (k == cnt - 1) {
                // exact power-of-2 renorm from lane 0's low element
                unsigned qu  = *(unsigned*)&q;
                unsigned ref = __shfl_sync(0xffffffffu, qu, 0);
                int ke = (int)((ref >> 7) & 0xFF) - 127;
                ksum += ke;
                unsigned su = (unsigned)(127 - ke) << 7;   // bf16 2^-ke
                su |= su << 16;
                q = __hmul2(q, u2b(su));
            }

            unsigned qu = *(unsigned*)&q;
            unsigned lo = __byte_perm(qu, qu, 0x1010);
            unsigned hi = __byte_perm(qu, qu, 0x3232);
            *(uint2*)&p_sh[wid][cur ^ 1][c0] = make_uint2(lo, hi);
            __syncwarp();
            cur ^= 1;
        }
        #pragma unroll
        for (int k = 0; k < CHUNK; ++k) fr[k] = fr2[k];
        c += CHUNK;
    }

    // ---- final transition into END (q holds my 2 final state values) ----
    float v = __bfloat162float(__low2bfloat16(q))  * et0
            + __bfloat162float(__high2bfloat16(q)) * et1;
    #pragma unroll
    for (int o = 16; o; o >>= 1) v += __shfl_xor_sync(0xffffffffu, v, o);
    if (lane == 0) {
        float forward = (float)ksum * 0.69314718055994531f + __logf(v);
        g_res[b] = forward - gs;
    }
}

__global__ void crf_reduce_kernel(float* __restrict__ out)
{
    const int tid  = threadIdx.x;
    const int lane = tid & 31;
    const int warp = tid >> 5;
    __shared__ float sh[2];

    float v = g_res[tid];
    #pragma unroll
    for (int o = 16; o; o >>= 1) v += __shfl_xor_sync(0xffffffffu, v, o);
    if (lane == 0) sh[warp] = v;
    __syncthreads();
    if (tid == 0) out[0] = sh[0] + sh[1];
}

extern "C" void kernel_launch(void* const* d_in, const int* in_sizes, int n_in,
                              void* d_out, int out_size)
{
    const float* feats = (const float*)d_in[0];
    const float* trans = (const float*)d_in[1];
    const int*   mask  = (const int*)d_in[2];
    const int*   tags  = (const int*)d_in[3];
    float* out = (float*)d_out;

    crf_forward_kernel<<<B_ / WPC, WPC * 32>>>(feats, trans, mask, tags);
    crf_reduce_kernel<<<1, 64>>>(out);
}

// round 10
// speedup vs baseline: 1.2875x; 1.2875x over previous
#include <cuda_runtime.h>
#include <cuda_bf16.h>

// CRF NLL, prob-domain. B=64, S=512, T=64 (START=62, END=63).
// R10: forward-backward split. Z = alpha_M * E * w_{M+1}:
//   fwd:  alpha_s = (alpha_{s-1} E) o ef_s           (M steps)
//   bwd:  w_s     = ef_s o (E w_{s+1}),  w_{len-1} = ef_{len-1} o eEND
// Both chains run in the SAME barrier interval (independent -> ILP), so
// interval count is ~(len-1)/2 instead of len-1. bf16 HFMA2 matvec,
// packed-shfl combine, exact power-of-2 renorm per chunk per chain.
//
// Inputs: d_in[0] feats f32 [B,S,T], d_in[1] transitions f32 [T,T],
//         d_in[2] mask i32 [B,S] (contiguous prefix), d_in[3] tags i32 [B,S]
// Output: f32 scalar sum_b (forward_b - gold_b)

#define B_    64
#define S_    512
#define T_    64
#define CHUNK 8

__device__ float g_res[B_];

static __device__ __forceinline__ __nv_bfloat162 u2b(unsigned u) {
    return *(__nv_bfloat162*)&u;
}
static __device__ __forceinline__ unsigned b2u(__nv_bfloat162 v) {
    return *(unsigned*)&v;
}
// exponent (unbiased) of max over 32 packed bf16 pairs in smem
static __device__ __forceinline__ int max_exp(const unsigned* p) {
    const uint4* pv = (const uint4*)p;
    uint4 u0 = pv[0], u1 = pv[1], u2 = pv[2], u3 = pv[3];
    __nv_bfloat162 m0, m1, m2, m3;
    m0 = __hmax2(u2b(u0.x), u2b(u0.y));
    m0 = __hmax2(m0, __hmax2(u2b(u0.z), u2b(u0.w)));
    m1 = __hmax2(u2b(u1.x), u2b(u1.y));
    m1 = __hmax2(m1, __hmax2(u2b(u1.z), u2b(u1.w)));
    m2 = __hmax2(u2b(u2.x), u2b(u2.y));
    m2 = __hmax2(m2, __hmax2(u2b(u2.z), u2b(u2.w)));
    m3 = __hmax2(u2b(u3.x), u2b(u3.y));
    m3 = __hmax2(m3, __hmax2(u2b(u3.z), u2b(u3.w)));
    __nv_bfloat162 mm = __hmax2(__hmax2(m0, m1), __hmax2(m2, m3));
    __nv_bfloat16  mx = __hmax(__low2bfloat16(mm), __high2bfloat16(mm));
    unsigned short bits = *(unsigned short*)&mx;
    return (int)((bits >> 7) & 0xFF) - 127;
}
static __device__ __forceinline__ __nv_bfloat16 pow2_bf16(int e) {
    unsigned short sb = (unsigned short)((e + 127) << 7);
    return *(__nv_bfloat16*)&sb;
}
// 16-deep bf16 matvec partial (2 x LDS.128 + 8 HFMA2) + packed cross-seg
// combine (2 shfl + hadd2) -> scalar total for this thread's column.
static __device__ __forceinline__ __nv_bfloat16 matvec16(
    const unsigned* pp, const __nv_bfloat162* e2)
{
    const uint4* pv = (const uint4*)pp;
    uint4 u0 = pv[0], u1 = pv[1];
    __nv_bfloat162 a0 = __hmul2(u2b(u0.x), e2[0]);
    __nv_bfloat162 a1 = __hmul2(u2b(u0.y), e2[1]);
    __nv_bfloat162 a2 = __hmul2(u2b(u0.z), e2[2]);
    __nv_bfloat162 a3 = __hmul2(u2b(u0.w), e2[3]);
    a0 = __hfma2(u2b(u1.x), e2[4], a0);
    a1 = __hfma2(u2b(u1.y), e2[5], a1);
    a2 = __hfma2(u2b(u1.z), e2[6], a2);
    a3 = __hfma2(u2b(u1.w), e2[7], a3);
    __nv_bfloat162 s = __hadd2(__hadd2(a0, a1), __hadd2(a2, a3));
    unsigned t = __shfl_xor_sync(0xffffffffu, b2u(s), 8);
    s = __hadd2(s, u2b(t));
    t = __shfl_xor_sync(0xffffffffu, b2u(s), 16);
    s = __hadd2(s, u2b(t));
    return __hadd(__low2bfloat16(s), __high2bfloat16(s));
}

__global__ __launch_bounds__(256, 1) void crf_forward_kernel(
    const float* __restrict__ feats,
    const float* __restrict__ trans,
    const int*   __restrict__ mask,
    const int*   __restrict__ tags)
{
    __shared__ __align__(16) float    trans_sh[T_ * T_];
    __shared__ __align__(16) unsigned a_sh[2][T_ / 2];   // alpha bf16 pairs
    __shared__ __align__(16) unsigned w_sh[2][T_ / 2];   // w bf16 pairs
    __shared__ __align__(16) __nv_bfloat16 fa_sh[CHUNK][T_];  // fwd emissions
    __shared__ __align__(16) __nv_bfloat16 fb_sh[CHUNK][T_];  // bwd emissions
    __shared__ int   tags_sh[S_];
    __shared__ float redg[8];
    __shared__ float redf[8];
    __shared__ int   redi[8];

    const int b    = blockIdx.x;
    const int tid  = threadIdx.x;
    const int lane = tid & 31;
    const int warp = tid >> 5;
    const int seg  = lane >> 3;                 // 0..3 : segment of 16
    const int j    = (warp << 3) | (lane & 7);  // 0..63 : output index
    const int r    = tid >> 6;                  // 0..3 : staging row group
    const int col  = tid & 63;                  // staging column

    const float* fbp   = feats + (size_t)b * S_ * T_;
    const int*   maskb = mask  + b * S_;
    const int*   tagsb = tags  + b * S_;

    // ---- stage transitions ----
    {
        const float4* t4 = (const float4*)trans;
        float4*       s4 = (float4*)trans_sh;
        #pragma unroll
        for (int i = 0; i < 4; ++i) s4[i * 256 + tid] = t4[i * 256 + tid];
    }
    // ---- tags + length ----
    int lenp = 0;
    #pragma unroll
    for (int k = 0; k < 2; ++k) {
        tags_sh[k * 256 + tid] = tagsb[k * 256 + tid];
        lenp += maskb[k * 256 + tid];
    }
    #pragma unroll
    for (int o = 16; o; o >>= 1) lenp += __shfl_xor_sync(0xffffffffu, lenp, o);
    if (lane == 0) redi[warp] = lenp;
    __syncthreads();
    int len = 0;
    #pragma unroll
    for (int w = 0; w < 8; ++w) len += redi[w];

    // ---- gold path score ----
    float g = 0.f;
    #pragma unroll
    for (int kk = 0; kk < 2; ++kk) {
        int s = kk * 256 + tid;
        if (s < len) {
            int tg = tags_sh[s];
            int pv = s ? tags_sh[s - 1] : (T_ - 2);
            g += fbp[s * T_ + tg] + trans_sh[pv * T_ + tg];
        }
    }
    if (tid == 0) g += trans_sh[tags_sh[len - 1] * T_ + (T_ - 1)];
    #pragma unroll
    for (int o = 16; o; o >>= 1) g += __shfl_xor_sync(0xffffffffu, g, o);
    if (lane == 0) redg[warp] = g;

    // ---- E slices: fwd column slice, bwd row slice ----
    __nv_bfloat162 ef2[8], eb2[8];
    #pragma unroll
    for (int m = 0; m < 8; ++m) {
        int i0 = seg * 16 + 2 * m;
        ef2[m] = __floats2bfloat162_rn(__expf(trans_sh[i0 * T_ + j]),
                                       __expf(trans_sh[(i0 + 1) * T_ + j]));
        eb2[m] = __floats2bfloat162_rn(__expf(trans_sh[j * T_ + i0]),
                                       __expf(trans_sh[j * T_ + i0 + 1]));
    }

    const int M      = (len - 2) >> 1;
    const int fsteps = M;               // fwd matvec steps
    const int bsteps = len - 2 - M;     // bwd matvec steps (>= fsteps)
    const int N      = bsteps;

    // ---- init alpha_0 and w_{len-1} ----
    if (tid < T_) {
        float a0 = __expf(fbp[tid] + trans_sh[(T_ - 2) * T_ + tid]);
        ((__nv_bfloat16*)a_sh[0])[tid] = __float2bfloat16(a0);
        float w0 = __expf(fbp[(len - 1) * T_ + tid] + trans_sh[tid * T_ + (T_ - 1)]);
        ((__nv_bfloat16*)w_sh[0])[tid] = __float2bfloat16(w0);
    }

    // ---- prefetch first chunk's emissions (fwd ascending, bwd descending) ----
    int n = 0;
    float frA0, frA1, frB0, frB1;
    {
        int ra0 = min(1 + n + r, S_ - 1), ra1 = min(5 + n + r, S_ - 1);
        frA0 = fbp[ra0 * T_ + col];
        frA1 = fbp[ra1 * T_ + col];
        int rb0 = max(len - 2 - n - r, 0), rb1 = max(len - 6 - n - r, 0);
        frB0 = fbp[rb0 * T_ + col];
        frB1 = fbp[rb1 * T_ + col];
    }
    __syncthreads();   // a_sh[0], w_sh[0], redg visible

    // ---- paired recurrence ----
    int cur = 0, ksumF = 0, ksumB = 0;

    while (n < N) {
        // stage exp(f) for this chunk
        fa_sh[r][col]     = __float2bfloat16(__expf(frA0));
        fa_sh[r + 4][col] = __float2bfloat16(__expf(frA1));
        fb_sh[r][col]     = __float2bfloat16(__expf(frB0));
        fb_sh[r + 4][col] = __float2bfloat16(__expf(frB1));

        // prefetch next chunk
        int nn = n + CHUNK;
        if (nn < N) {
            int ra0 = min(1 + nn + r, S_ - 1), ra1 = min(5 + nn + r, S_ - 1);
            frA0 = fbp[ra0 * T_ + col];
            frA1 = fbp[ra1 * T_ + col];
            int rb0 = max(len - 2 - nn - r, 0), rb1 = max(len - 6 - nn - r, 0);
            frB0 = fbp[rb0 * T_ + col];
            frB1 = fbp[rb1 * T_ + col];
        }

        // exact power-of-2 renorm per chain (redundant per-thread, off-path)
        __nv_bfloat16 sF = __float2bfloat16(1.0f), sB;
        const bool liveF = (n < fsteps);
        if (liveF) { int ke = max_exp(a_sh[cur]); ksumF += ke; sF = pow2_bf16(-ke); }
        { int ke = max_exp(w_sh[cur]); ksumB += ke; sB = pow2_bf16(-ke); }

        const int cnt = min(CHUNK, N - n);
        __syncthreads();   // emissions visible; all prior reads done

        #pragma unroll
        for (int k = 0; k < CHUNK; ++k) {
            if (k >= cnt) break;                 // block-uniform
            const bool doF = (n + k) < fsteps;   // block-uniform
            // backward step (always live while n+k < N)
            __nv_bfloat16 qb = matvec16(w_sh[cur] + seg * 8, eb2);
            qb = __hmul(qb, fb_sh[k][j]);
            // forward step
            __nv_bfloat16 qa;
            if (doF) {
                qa = matvec16(a_sh[cur] + seg * 8, ef2);
                qa = __hmul(qa, fa_sh[k][j]);
            }
            if (k == 0) {
                qb = __hmul(qb, sB);
                if (doF) qa = __hmul(qa, sF);
            }
            if (seg == 0) {
                ((__nv_bfloat16*)w_sh[cur ^ 1])[j] = qb;
                if (doF) ((__nv_bfloat16*)a_sh[cur ^ 1])[j] = qa;
            }
            __syncthreads();
            cur ^= 1;
        }
        n += CHUNK;
    }

    // ---- stitch: Z = sum_j (alpha_M E)_j * w_{M+1,j} ----
    {
        __nv_bfloat16 vh = matvec16(a_sh[fsteps & 1] + seg * 8, ef2);
        float vj = __bfloat162float(vh);
        float wj = __bfloat162float(((const __nv_bfloat16*)w_sh[bsteps & 1])[j]);
        float z  = vj * wj;
        #pragma unroll
        for (int o = 16; o; o >>= 1) z += __shfl_xor_sync(0xffffffffu, z, o);
        if (lane == 0) redf[warp] = z;
    }
    __syncthreads();
    if (tid == 0) {
        float tot = 0.f;
        #pragma unroll
        for (int w = 0; w < 8; ++w) tot += redf[w];
        tot *= 0.25f;   // each j counted by 4 seg-threads
        float forward = (float)(ksumF + ksumB) * 0.69314718055994531f
                        + __logf(tot);
        float gold = 0.f;
        #pragma unroll
        for (int w = 0; w < 8; ++w) gold += redg[w];
        g_res[b] = forward - gold;
    }
}

__global__ void crf_reduce_kernel(float* __restrict__ out)
{
    const int tid  = threadIdx.x;
    const int lane = tid & 31;
    const int warp = tid >> 5;
    __shared__ float sh[2];

    float v = g_res[tid];
    #pragma unroll
    for (int o = 16; o; o >>= 1) v += __shfl_xor_sync(0xffffffffu, v, o);
    if (lane == 0) sh[warp] = v;
    __syncthreads();
    if (tid == 0) out[0] = sh[0] + sh[1];
}

extern "C" void kernel_launch(void* const* d_in, const int* in_sizes, int n_in,
                              void* d_out, int out_size)
{
    const float* feats = (const float*)d_in[0];
    const float* trans = (const float*)d_in[1];
    const int*   mask  = (const int*)d_in[2];
    const int*   tags  = (const int*)d_in[3];
    float* out = (float*)d_out;

    crf_forward_kernel<<<B_, 256>>>(feats, trans, mask, tags);
    crf_reduce_kernel<<<1, 64>>>(out);
}

// round 11
// speedup vs baseline: 1.8159x; 1.4104x over previous
#include <cuda_runtime.h>
#include <cuda_bf16.h>

// CRF NLL, prob-domain. B=64, S=512, T=64 (START=62, END=63).
// R11: forward-backward split with FUSED pair step:
//   - branch-free: N = (len-2)/2 unconditional paired steps, parity step outside
//   - both chains share ONE packed shfl reduction (hA,hB in one bf16x2)
//   - emissions staged interleaved (fa,fb) so one LDS.32 feeds both chains
//   - exact power-of-2 renorm per chunk per chain (packed scale multiply)
//
// Inputs: d_in[0] feats f32 [B,S,T], d_in[1] transitions f32 [T,T],
//         d_in[2] mask i32 [B,S] (contiguous prefix), d_in[3] tags i32 [B,S]
// Output: f32 scalar sum_b (forward_b - gold_b)

#define B_    64
#define S_    512
#define T_    64
#define CHUNK 8

__device__ float g_res[B_];

static __device__ __forceinline__ __nv_bfloat162 u2b(unsigned u) {
    return *(__nv_bfloat162*)&u;
}
static __device__ __forceinline__ unsigned b2u(__nv_bfloat162 v) {
    return *(unsigned*)&v;
}
static __device__ __forceinline__ int max_exp(const unsigned* p) {
    const uint4* pv = (const uint4*)p;
    uint4 u0 = pv[0], u1 = pv[1], u2 = pv[2], u3 = pv[3];
    __nv_bfloat162 m0, m1, m2, m3;
    m0 = __hmax2(u2b(u0.x), u2b(u0.y));
    m0 = __hmax2(m0, __hmax2(u2b(u0.z), u2b(u0.w)));
    m1 = __hmax2(u2b(u1.x), u2b(u1.y));
    m1 = __hmax2(m1, __hmax2(u2b(u1.z), u2b(u1.w)));
    m2 = __hmax2(u2b(u2.x), u2b(u2.y));
    m2 = __hmax2(m2, __hmax2(u2b(u2.z), u2b(u2.w)));
    m3 = __hmax2(u2b(u3.x), u2b(u3.y));
    m3 = __hmax2(m3, __hmax2(u2b(u3.z), u2b(u3.w)));
    __nv_bfloat162 mm = __hmax2(__hmax2(m0, m1), __hmax2(m2, m3));
    __nv_bfloat16  mx = __hmax(__low2bfloat16(mm), __high2bfloat16(mm));
    unsigned short bits = *(unsigned short*)&mx;
    return (int)((bits >> 7) & 0xFF) - 127;
}
static __device__ __forceinline__ __nv_bfloat16 pow2_bf16(int e) {
    unsigned short sb = (unsigned short)((e + 127) << 7);
    return *(__nv_bfloat16*)&sb;
}
// single-chain 16-deep matvec + own shfl combine (used only in stitch/parity)
static __device__ __forceinline__ __nv_bfloat16 matvec16(
    const unsigned* pp, const __nv_bfloat162* e2)
{
    const uint4* pv = (const uint4*)pp;
    uint4 u0 = pv[0], u1 = pv[1];
    __nv_bfloat162 a0 = __hmul2(u2b(u0.x), e2[0]);
    __nv_bfloat162 a1 = __hmul2(u2b(u0.y), e2[1]);
    __nv_bfloat162 a2 = __hmul2(u2b(u0.z), e2[2]);
    __nv_bfloat162 a3 = __hmul2(u2b(u0.w), e2[3]);
    a0 = __hfma2(u2b(u1.x), e2[4], a0);
    a1 = __hfma2(u2b(u1.y), e2[5], a1);
    a2 = __hfma2(u2b(u1.z), e2[6], a2);
    a3 = __hfma2(u2b(u1.w), e2[7], a3);
    __nv_bfloat162 s = __hadd2(__hadd2(a0, a1), __hadd2(a2, a3));
    unsigned t = __shfl_xor_sync(0xffffffffu, b2u(s), 8);
    s = __hadd2(s, u2b(t));
    t = __shfl_xor_sync(0xffffffffu, b2u(s), 16);
    s = __hadd2(s, u2b(t));
    return __hadd(__low2bfloat16(s), __high2bfloat16(s));
}

__global__ __launch_bounds__(256, 1) void crf_forward_kernel(
    const float* __restrict__ feats,
    const float* __restrict__ trans,
    const int*   __restrict__ mask,
    const int*   __restrict__ tags)
{
    __shared__ __align__(16) float    trans_sh[T_ * T_];
    __shared__ __align__(16) unsigned a_sh[2][T_ / 2];   // alpha bf16 pairs
    __shared__ __align__(16) unsigned w_sh[2][T_ / 2];   // w bf16 pairs
    __shared__ __align__(16) __nv_bfloat162 fab_sh[CHUNK][T_]; // (fa,fb) pairs
    __shared__ int   tags_sh[S_];
    __shared__ float redg[8];
    __shared__ float redf[8];
    __shared__ int   redi[8];

    const int b    = blockIdx.x;
    const int tid  = threadIdx.x;
    const int lane = tid & 31;
    const int warp = tid >> 5;
    const int seg  = lane >> 3;                 // 0..3 : segment of 16
    const int j    = (warp << 3) | (lane & 7);  // 0..63 : output index
    const int r    = tid >> 6;                  // 0..3 : staging row group
    const int col  = tid & 63;                  // staging column

    const float* fbp   = feats + (size_t)b * S_ * T_;
    const int*   maskb = mask  + b * S_;
    const int*   tagsb = tags  + b * S_;

    // ---- stage transitions ----
    {
        const float4* t4 = (const float4*)trans;
        float4*       s4 = (float4*)trans_sh;
        #pragma unroll
        for (int i = 0; i < 4; ++i) s4[i * 256 + tid] = t4[i * 256 + tid];
    }
    // ---- tags + length ----
    int lenp = 0;
    #pragma unroll
    for (int k = 0; k < 2; ++k) {
        tags_sh[k * 256 + tid] = tagsb[k * 256 + tid];
        lenp += maskb[k * 256 + tid];
    }
    #pragma unroll
    for (int o = 16; o; o >>= 1) lenp += __shfl_xor_sync(0xffffffffu, lenp, o);
    if (lane == 0) redi[warp] = lenp;
    __syncthreads();
    int len = 0;
    #pragma unroll
    for (int w = 0; w < 8; ++w) len += redi[w];

    // ---- gold path score ----
    float g = 0.f;
    #pragma unroll
    for (int kk = 0; kk < 2; ++kk) {
        int s = kk * 256 + tid;
        if (s < len) {
            int tg = tags_sh[s];
            int pv = s ? tags_sh[s - 1] : (T_ - 2);
            g += fbp[s * T_ + tg] + trans_sh[pv * T_ + tg];
        }
    }
    if (tid == 0) g += trans_sh[tags_sh[len - 1] * T_ + (T_ - 1)];
    #pragma unroll
    for (int o = 16; o; o >>= 1) g += __shfl_xor_sync(0xffffffffu, g, o);
    if (lane == 0) redg[warp] = g;

    // ---- E slices: fwd column slice, bwd row slice ----
    __nv_bfloat162 ef2[8], eb2[8];
    #pragma unroll
    for (int m = 0; m < 8; ++m) {
        int i0 = seg * 16 + 2 * m;
        ef2[m] = __floats2bfloat162_rn(__expf(trans_sh[i0 * T_ + j]),
                                       __expf(trans_sh[(i0 + 1) * T_ + j]));
        eb2[m] = __floats2bfloat162_rn(__expf(trans_sh[j * T_ + i0]),
                                       __expf(trans_sh[j * T_ + i0 + 1]));
    }

    const int N = (len - 2) >> 1;        // paired steps
    const int p = (len - 2) & 1;         // parity: extra fwd step

    // ---- init alpha_0 and w_{len-1} ----
    if (tid < T_) {
        float a0 = __expf(fbp[tid] + trans_sh[(T_ - 2) * T_ + tid]);
        ((__nv_bfloat16*)a_sh[0])[tid] = __float2bfloat16(a0);
        float w0 = __expf(fbp[(len - 1) * T_ + tid] + trans_sh[tid * T_ + (T_ - 1)]);
        ((__nv_bfloat16*)w_sh[0])[tid] = __float2bfloat16(w0);
    }

    // ---- prefetch first chunk's emissions ----
    int n = 0;
    float frA0, frA1, frB0, frB1;
    {
        int ra0 = min(1 + r, S_ - 1), ra1 = min(5 + r, S_ - 1);
        frA0 = fbp[ra0 * T_ + col];
        frA1 = fbp[ra1 * T_ + col];
        int rb0 = max(len - 2 - r, 0), rb1 = max(len - 6 - r, 0);
        frB0 = fbp[rb0 * T_ + col];
        frB1 = fbp[rb1 * T_ + col];
    }
    __syncthreads();   // a_sh[0], w_sh[0], redg visible

    // ---- fused paired recurrence ----
    int cur = 0, ksumF = 0, ksumB = 0;

    while (n < N) {
        // stage interleaved (fa, fb) emissions for this chunk
        fab_sh[r][col]     = __floats2bfloat162_rn(__expf(frA0), __expf(frB0));
        fab_sh[r + 4][col] = __floats2bfloat162_rn(__expf(frA1), __expf(frB1));

        // prefetch next chunk
        int nn = n + CHUNK;
        if (nn < N) {
            int ra0 = min(1 + nn + r, S_ - 1), ra1 = min(5 + nn + r, S_ - 1);
            frA0 = fbp[ra0 * T_ + col];
            frA1 = fbp[ra1 * T_ + col];
            int rb0 = max(len - 2 - nn - r, 0), rb1 = max(len - 6 - nn - r, 0);
            frB0 = fbp[rb0 * T_ + col];
            frB1 = fbp[rb1 * T_ + col];
        }

        // exact power-of-2 renorm per chain, packed scale (off critical path)
        __nv_bfloat162 scale2;
        {
            int keF = max_exp(a_sh[cur]);  ksumF += keF;
            int keB = max_exp(w_sh[cur]);  ksumB += keB;
            scale2 = __halves2bfloat162(pow2_bf16(-keF), pow2_bf16(-keB));
        }

        const int cnt = min(CHUNK, N - n);
        __syncthreads();   // emissions visible; all prior reads done

        #pragma unroll
        for (int k = 0; k < CHUNK; ++k) {
            if (k >= cnt) break;   // block-uniform
            __nv_bfloat162 f2 = fab_sh[k][j];   // (fa, fb) one LDS.32
            const uint4* pa = (const uint4*)(a_sh[cur] + seg * 8);
            const uint4* pb = (const uint4*)(w_sh[cur] + seg * 8);
            uint4 ua0 = pa[0], ua1 = pa[1];
            uint4 ub0 = pb[0], ub1 = pb[1];
            // interleaved dual HFMA2 trees (independent chains)
            __nv_bfloat162 aA0 = __hmul2(u2b(ua0.x), ef2[0]);
            __nv_bfloat162 aB0 = __hmul2(u2b(ub0.x), eb2[0]);
            __nv_bfloat162 aA1 = __hmul2(u2b(ua0.y), ef2[1]);
            __nv_bfloat162 aB1 = __hmul2(u2b(ub0.y), eb2[1]);
            __nv_bfloat162 aA2 = __hmul2(u2b(ua0.z), ef2[2]);
            __nv_bfloat162 aB2 = __hmul2(u2b(ub0.z), eb2[2]);
            __nv_bfloat162 aA3 = __hmul2(u2b(ua0.w), ef2[3]);
            __nv_bfloat162 aB3 = __hmul2(u2b(ub0.w), eb2[3]);
            aA0 = __hfma2(u2b(ua1.x), ef2[4], aA0);
            aB0 = __hfma2(u2b(ub1.x), eb2[4], aB0);
            aA1 = __hfma2(u2b(ua1.y), ef2[5], aA1);
            aB1 = __hfma2(u2b(ub1.y), eb2[5], aB1);
            aA2 = __hfma2(u2b(ua1.z), ef2[6], aA2);
            aB2 = __hfma2(u2b(ub1.z), eb2[6], aB2);
            aA3 = __hfma2(u2b(ua1.w), ef2[7], aA3);
            aB3 = __hfma2(u2b(ub1.w), eb2[7], aB3);
            __nv_bfloat162 sA = __hadd2(__hadd2(aA0, aA1), __hadd2(aA2, aA3));
            __nv_bfloat162 sB = __hadd2(__hadd2(aB0, aB1), __hadd2(aB2, aB3));
            // horizontal fold each chain, pack, ONE shfl bundle for both
            __nv_bfloat16 hA = __hadd(__low2bfloat16(sA), __high2bfloat16(sA));
            __nv_bfloat16 hB = __hadd(__low2bfloat16(sB), __high2bfloat16(sB));
            __nv_bfloat162 h2 = __halves2bfloat162(hA, hB);
            unsigned t = __shfl_xor_sync(0xffffffffu, b2u(h2), 8);
            h2 = __hadd2(h2, u2b(t));
            t = __shfl_xor_sync(0xffffffffu, b2u(h2), 16);
            h2 = __hadd2(h2, u2b(t));
            // packed epilogue: emissions, renorm scale
            __nv_bfloat162 q2 = __hmul2(h2, f2);
            if (k == 0) q2 = __hmul2(q2, scale2);
            if (seg == 0) {
                ((__nv_bfloat16*)a_sh[cur ^ 1])[j] = __low2bfloat16(q2);
                ((__nv_bfloat16*)w_sh[cur ^ 1])[j] = __high2bfloat16(q2);
            }
            __syncthreads();
            cur ^= 1;
        }
        n += CHUNK;
    }
    // after loop: a_sh[cur] = alpha_N, w_sh[cur] = w_{N+p+1}

    // ---- parity step: one extra forward step (emission row 1+N) ----
    int aidx = cur;
    if (p) {
        __nv_bfloat16 qa = matvec16(a_sh[cur] + seg * 8, ef2);
        qa = __hmul(qa, __float2bfloat16(__expf(fbp[(1 + N) * T_ + j])));
        if (seg == 0) ((__nv_bfloat16*)a_sh[cur ^ 1])[j] = qa;
        aidx = cur ^ 1;
        __syncthreads();
    }

    // ---- stitch: Z = sum_j (alpha_M E)_j * w_{M+1,j}, M = N+p ----
    {
        __nv_bfloat16 vh = matvec16(a_sh[aidx] + seg * 8, ef2);
        float vj = __bfloat162float(vh);
        float wj = __bfloat162float(((const __nv_bfloat16*)w_sh[cur])[j]);
        float z  = vj * wj;
        #pragma unroll
        for (int o = 16; o; o >>= 1) z += __shfl_xor_sync(0xffffffffu, z, o);
        if (lane == 0) redf[warp] = z;
    }
    __syncthreads();
    if (tid == 0) {
        float tot = 0.f;
        #pragma unroll
        for (int w = 0; w < 8; ++w) tot += redf[w];
        tot *= 0.25f;   // each j counted by 4 seg-threads
        float forward = (float)(ksumF + ksumB) * 0.69314718055994531f
                        + __logf(tot);
        float gold = 0.f;
        #pragma unroll
        for (int w = 0; w < 8; ++w) gold += redg[w];
        g_res[b] = forward - gold;
    }
}

__global__ void crf_reduce_kernel(float* __restrict__ out)
{
    const int tid  = threadIdx.x;
    const int lane = tid & 31;
    const int warp = tid >> 5;
    __shared__ float sh[2];

    float v = g_res[tid];
    #pragma unroll
    for (int o = 16; o; o >>= 1) v += __shfl_xor_sync(0xffffffffu, v, o);
    if (lane == 0) sh[warp] = v;
    __syncthreads();
    if (tid == 0) out[0] = sh[0] + sh[1];
}

extern "C" void kernel_launch(void* const* d_in, const int* in_sizes, int n_in,
                              void* d_out, int out_size)
{
    const float* feats = (const float*)d_in[0];
    const float* trans = (const float*)d_in[1];
    const int*   mask  = (const int*)d_in[2];
    const int*   tags  = (const int*)d_in[3];
    float* out = (float*)d_out;

    crf_forward_kernel<<<B_, 256>>>(feats, trans, mask, tags);
    crf_reduce_kernel<<<1, 64>>>(out);
}